// round 10
// baseline (speedup 1.0000x reference)
#include <cuda_runtime.h>
#include <cuda_fp16.h>

// B=8192, T=16, M=16, V=256 fixed.
#define INS_DEL 10.0f
#define FIRST_CHAR_COST 10.0f

#define WARPS_PER_BLOCK 4
#define THREADS_PER_BLOCK (WARPS_PER_BLOCK * 32)

#define K10 4.5399929762484854e-05f          // e^{-10}

// Per-warp shared:
//   E[t][v]  : exp(logits) half, 16 rows x 512B, XOR granule swizzle (^row&7)
//   Bst[n][k]: gathered phon rows as half, same geometry/swizzle
//   S[t][m]  : exp(-sub) fp32, stride 18
#define E_HALVES (16 * 256)
#define B_HALVES (16 * 256)
#define SSTRIDE 18
#define S_FLOATS 292

__device__ __forceinline__ void ldsm_x4(unsigned &r0, unsigned &r1,
                                        unsigned &r2, unsigned &r3,
                                        unsigned saddr) {
    asm volatile("ldmatrix.sync.aligned.m8n8.x4.shared.b16 {%0,%1,%2,%3}, [%4];\n"
                 : "=r"(r0), "=r"(r1), "=r"(r2), "=r"(r3) : "r"(saddr));
}

__device__ __forceinline__ void mma16816(float d[4],
                                         unsigned a0, unsigned a1,
                                         unsigned a2, unsigned a3,
                                         unsigned b0, unsigned b1) {
    asm volatile("mma.sync.aligned.m16n8k16.row.col.f32.f16.f16.f32 "
                 "{%0,%1,%2,%3}, {%4,%5,%6,%7}, {%8,%9}, {%0,%1,%2,%3};\n"
                 : "+f"(d[0]), "+f"(d[1]), "+f"(d[2]), "+f"(d[3])
                 : "r"(a0), "r"(a1), "r"(a2), "r"(a3), "r"(b0), "r"(b1));
}

__device__ __forceinline__ unsigned pack_h2(float x, float y) {
    __half2 h = __floats2half2_rn(x, y);
    return *(unsigned*)&h;
}

__global__ void __launch_bounds__(THREADS_PER_BLOCK, 3)
rhyme_dp_kernel(const float* __restrict__ logits,
                const int* __restrict__ tgt,
                const float* __restrict__ phon,
                float* __restrict__ out, int B)
{
    __shared__ __half sE[WARPS_PER_BLOCK][E_HALVES];
    __shared__ __half sB[WARPS_PER_BLOCK][B_HALVES];
    __shared__ float  sS[WARPS_PER_BLOCK][S_FLOATS];

    const int w    = threadIdx.x >> 5;
    const int lane = threadIdx.x & 31;
    const int b    = blockIdx.x * WARPS_PER_BLOCK + w;
    if (b >= B) return;

    __half* E   = sE[w];
    __half* Bst = sB[w];
    float*  S   = sS[w];

    const float* lg = logits + (size_t)b * (16 * 256);
    const int m = lane & 15;

    const int gm = tgt[b * 16 + m];
    const int g0 = __shfl_sync(0xffffffffu, gm, 0);

    // -------- Phase 1: raw exp -> shared E (half, swizzled) -----------------
    {
        const float4* rows = (const float4*)lg;   // 16 rows x 64 float4
        const int li = lane * 2;
#pragma unroll 4
        for (int t = 0; t < 16; ++t) {
            float4 x0 = rows[t * 64 + li];
            float4 x1 = rows[t * 64 + li + 1];
            unsigned h[4];
            h[0] = pack_h2(__expf(x0.x), __expf(x0.y));
            h[1] = pack_h2(__expf(x0.z), __expf(x0.w));
            h[2] = pack_h2(__expf(x1.x), __expf(x1.y));
            h[3] = pack_h2(__expf(x1.z), __expf(x1.w));
            const int gr = lane ^ (t & 7);
            *(uint4*)(E + t * 256 + gr * 8) = *(uint4*)h;
        }
    }

    // -------- Phase 1.5: stage phon rows (coalesced) -> shared Bst ----------
    // Bst[n][k] = phon[tgt[b][n]][k] as half; row stride 512B, swizzle ^n&7.
    {
#pragma unroll 4
        for (int j = 0; j < 16; ++j) {
            const int gn = __shfl_sync(0xffffffffu, gm, j);
            const float4* prow = (const float4*)(phon + (size_t)gn * 256);
            float4 c0 = __ldg(prow + lane * 2);
            float4 c1 = __ldg(prow + lane * 2 + 1);
            unsigned h[4];
            h[0] = pack_h2(c0.x, c0.y);
            h[1] = pack_h2(c0.z, c0.w);
            h[2] = pack_h2(c1.x, c1.y);
            h[3] = pack_h2(c1.z, c1.w);
            const int gr = lane ^ (j & 7);
            *(uint4*)(Bst + j * 256 + gr * 8) = *(uint4*)h;
        }
    }
    __syncwarp();

    // -------- Phase 2: [sub_raw | Z] = E @ [Bst^T | ones] via HMMA ----------
    // A: ldmatrix on E (row-major [t][v]). B: non-trans ldmatrix on Bst
    // (row-major [n][k]) IS the col-major fragment of B[k][n].
    float d0[4] = {0.f, 0.f, 0.f, 0.f};
    float d1[4] = {0.f, 0.f, 0.f, 0.f};
    float d2[4] = {0.f, 0.f, 0.f, 0.f};
    float z0_lane0;
    {
        const unsigned ebase = (unsigned)__cvta_generic_to_shared(E);
        const unsigned bbase = (unsigned)__cvta_generic_to_shared(Bst);

        // A addressing: row r = lane&15, granule (kt*2 + lane>>4) ^ (r&7)
        const unsigned ar  = lane & 15;
        const unsigned arx = ar & 7;
        const unsigned ahi = lane >> 4;
        const unsigned arow = ebase + ar * 512;

        // B addressing: tiles [n0-7,k0-7],[n0-7,k8-15],[n8-15,k0-7],[n8-15,k8-15]
        const unsigned bn   = (lane & 7) + ((lane >> 4) & 1) * 8;
        const unsigned bnx  = bn & 7;
        const unsigned bsel = (lane >> 3) & 1;
        const unsigned brow = bbase + bn * 512;

        const unsigned bone = (lane < 4) ? pack_h2(1.0f, 1.0f) : 0u;

#pragma unroll
        for (int kt = 0; kt < 16; ++kt) {
            unsigned a0, a1, a2, a3;
            const unsigned ga = (unsigned)(kt * 2) + ahi;
            ldsm_x4(a0, a1, a2, a3, arow + ((ga ^ arx) << 4));

            unsigned b00, b01, b10, b11;
            const unsigned gb = (unsigned)(kt * 2) + bsel;
            ldsm_x4(b00, b01, b10, b11, brow + ((gb ^ bnx) << 4));

            mma16816(d0, a0, a1, a2, a3, b00, b01);
            mma16816(d1, a0, a1, a2, a3, b10, b11);
            mma16816(d2, a0, a1, a2, a3, bone, bone);
        }

        // -------- writeback: S[t][m] = exp(-sub[t][m]) ----------------------
        const float zlo = __shfl_sync(0xffffffffu, d2[0], lane & ~3);
        const float zhi = __shfl_sync(0xffffffffu, d2[2], lane & ~3);
        z0_lane0 = __shfl_sync(0xffffffffu, d2[0], 0);   // Z[0]
        const float rzlo = -__fdividef(1.0f, zlo);
        const float rzhi = -__fdividef(1.0f, zhi);

        const int tq = lane >> 2;
        const int mc = (lane & 3) * 2;
        *(float2*)(S + tq * SSTRIDE + mc) =
            make_float2(__expf(d0[0] * rzlo), __expf(d0[1] * rzlo));
        *(float2*)(S + (tq + 8) * SSTRIDE + mc) =
            make_float2(__expf(d0[2] * rzhi), __expf(d0[3] * rzhi));
        *(float2*)(S + tq * SSTRIDE + mc + 8) =
            make_float2(__expf(d1[0] * rzlo), __expf(d1[1] * rzlo));
        *(float2*)(S + (tq + 8) * SSTRIDE + mc + 8) =
            make_float2(__expf(d1[2] * rzhi), __expf(d1[3] * rzhi));
    }
    __syncwarp();

    // -------- Phase 3: soft-DP wavefront in w-domain (w = exp(-dp)) ---------
    // w(i,j) = e^-10 * (w_up + w_left) + w_diag * exp(-sub[i-1][j-1])
    const float em1 = __expf(-10.0f * (float)(m + 1));   // w(0, m+1)
    const float em  = __expf(-10.0f * (float)m);         // w(0, m)
    float bl = K10;    // lane-0 running e^{-10*i}
    float bd = 1.0f;   // lane-0 running e^{-10*(i-1)}

    float cur = 0.0f, prev = 0.0f;
#pragma unroll
    for (int s = 0; s <= 30; ++s) {
        float leftv = __shfl_up_sync(0xffffffffu, cur, 1);
        float diagv = __shfl_up_sync(0xffffffffu, prev, 1);
        const int i = s - m + 1;
        const bool active = (i >= 1) && (i <= 16);

        float up = cur;
        if (i == 1) { up = em1; diagv = em; }
        if (m == 0) { leftv = bl; diagv = bd; }

        const int si = active ? (s - m) : 0;
        const float es = S[si * SSTRIDE + m];

        const float val = K10 * (up + leftv) + diagv * es;

        if (active) { prev = cur; cur = val; }
        bd = bl; bl *= K10;
    }

    // -------- Phase 4: final log + first-char term + output -----------------
    if (lane == 15) {
        // E row 0: swizzle key = 0, so direct index is valid.
        const float fm = __half2float(E[g0]) * __fdividef(1.0f, z0_lane0);
        out[b] = -__logf(cur) + FIRST_CHAR_COST * (1.0f - fm);
    }
}

extern "C" void kernel_launch(void* const* d_in, const int* in_sizes, int n_in,
                              void* d_out, int out_size)
{
    const float* logits = (const float*)d_in[0];   // tail_logits (B,T,V) f32
    const int*   tgt    = (const int*)  d_in[1];   // target_idx  (B,M) i32
    const float* phon   = (const float*)d_in[2];   // phon_cost   (V,V) f32
    float* out = (float*)d_out;
    const int B = out_size;                        // 8192

    const int grid = (B + WARPS_PER_BLOCK - 1) / WARPS_PER_BLOCK;
    rhyme_dp_kernel<<<grid, THREADS_PER_BLOCK>>>(logits, tgt, phon, out, B);
}

// round 11
// speedup vs baseline: 1.0471x; 1.0471x over previous
#include <cuda_runtime.h>
#include <cuda_fp16.h>

// B=8192, T=16, M=16, V=256 fixed.
#define INS_DEL 10.0f
#define FIRST_CHAR_COST 10.0f

#define WARPS_PER_BLOCK 4
#define THREADS_PER_BLOCK (WARPS_PER_BLOCK * 32)

#define K10 4.5399929762484854e-05f          // e^{-10}

// Per-warp shared (k-chunked, 2 chunks of 128):
//   Ec[t][k] : exp(logits) half, 16 rows x 256B, XOR granule swizzle (^t&7)
//   Bc[n][k] : gathered phon rows half, same geometry/swizzle
//   S[t][m]  : exp(-sub) fp32, stride 18
#define EC_HALVES (16 * 128)                 // 4096 B
#define BC_HALVES (16 * 128)                 // 4096 B
#define SSTRIDE 18
#define S_FLOATS 292

__device__ __forceinline__ void ldsm_x4(unsigned &r0, unsigned &r1,
                                        unsigned &r2, unsigned &r3,
                                        unsigned saddr) {
    asm volatile("ldmatrix.sync.aligned.m8n8.x4.shared.b16 {%0,%1,%2,%3}, [%4];\n"
                 : "=r"(r0), "=r"(r1), "=r"(r2), "=r"(r3) : "r"(saddr));
}

__device__ __forceinline__ void mma16816(float d[4],
                                         unsigned a0, unsigned a1,
                                         unsigned a2, unsigned a3,
                                         unsigned b0, unsigned b1) {
    asm volatile("mma.sync.aligned.m16n8k16.row.col.f32.f16.f16.f32 "
                 "{%0,%1,%2,%3}, {%4,%5,%6,%7}, {%8,%9}, {%0,%1,%2,%3};\n"
                 : "+f"(d[0]), "+f"(d[1]), "+f"(d[2]), "+f"(d[3])
                 : "r"(a0), "r"(a1), "r"(a2), "r"(a3), "r"(b0), "r"(b1));
}

__device__ __forceinline__ unsigned pack_h2(float x, float y) {
    __half2 h = __floats2half2_rn(x, y);
    return *(unsigned*)&h;
}

__global__ void __launch_bounds__(THREADS_PER_BLOCK, 6)
rhyme_dp_kernel(const float* __restrict__ logits,
                const int* __restrict__ tgt,
                const float* __restrict__ phon,
                float* __restrict__ out, int B)
{
    __shared__ __half sE[WARPS_PER_BLOCK][EC_HALVES];
    __shared__ __half sB[WARPS_PER_BLOCK][BC_HALVES];
    __shared__ float  sS[WARPS_PER_BLOCK][S_FLOATS];

    const int w    = threadIdx.x >> 5;
    const int lane = threadIdx.x & 31;
    const int b    = blockIdx.x * WARPS_PER_BLOCK + w;
    if (b >= B) return;

    __half* Ec = sE[w];
    __half* Bc = sB[w];
    float*  S  = sS[w];

    const float* lg = logits + (size_t)b * (16 * 256);
    const int m = lane & 15;

    const int gm = tgt[b * 16 + m];
    const int g0 = __shfl_sync(0xffffffffu, gm, 0);

    // accumulators persist across k-chunks
    float d0[4] = {0.f, 0.f, 0.f, 0.f};
    float d1[4] = {0.f, 0.f, 0.f, 0.f};
    float d2[4] = {0.f, 0.f, 0.f, 0.f};

    // ldmatrix addressing (constants across chunks)
    const unsigned ebase = (unsigned)__cvta_generic_to_shared(Ec);
    const unsigned bbase = (unsigned)__cvta_generic_to_shared(Bc);
    const unsigned ar  = lane & 15;          // A tile row
    const unsigned arx = ar & 7;
    const unsigned ahi = lane >> 4;
    const unsigned arow = ebase + ar * 256;
    const unsigned bn   = (lane & 7) + ((lane >> 4) & 1) * 8;   // B tile row
    const unsigned bnx  = bn & 7;
    const unsigned bsel = (lane >> 3) & 1;
    const unsigned brow = bbase + bn * 256;
    const unsigned bone = (lane < 4) ? pack_h2(1.0f, 1.0f) : 0u;

#pragma unroll
    for (int c = 0; c < 2; ++c) {
        // ---- stage E chunk: exp(logits[t][c*128 .. +128)) -------------------
        // per iter: 2 rows (lane>>4), lane covers 8 cols -> 16B granule
        {
            const int col8 = (lane & 15);    // granule index within row
            const float4* base = (const float4*)(lg + c * 128) + col8 * 2;
#pragma unroll
            for (int i = 0; i < 8; ++i) {
                const int t = 2 * i + (lane >> 4);
                float4 x0 = base[t * 64];
                float4 x1 = base[t * 64 + 1];
                unsigned h[4];
                h[0] = pack_h2(__expf(x0.x), __expf(x0.y));
                h[1] = pack_h2(__expf(x0.z), __expf(x0.w));
                h[2] = pack_h2(__expf(x1.x), __expf(x1.y));
                h[3] = pack_h2(__expf(x1.z), __expf(x1.w));
                const int gs = col8 ^ (t & 7);
                *(uint4*)(Ec + t * 128 + gs * 8) = *(uint4*)h;
            }
        }

        // ---- stage B chunk: phon[gn_j][c*128 .. +128) (coalesced) -----------
        {
#pragma unroll
            for (int j = 0; j < 16; ++j) {
                const int gn = __shfl_sync(0xffffffffu, gm, j);
                float4 cv = __ldg((const float4*)(phon + (size_t)gn * 256 + c * 128) + lane);
                unsigned h0 = pack_h2(cv.x, cv.y);
                unsigned h1 = pack_h2(cv.z, cv.w);
                const int k16 = lane >> 1;                  // granule
                const int gs = (k16 ^ (j & 7)) * 8 + (lane & 1) * 4;
                *(uint2*)(Bc + j * 128 + gs) = make_uint2(h0, h1);
            }
        }
        __syncwarp();

        // ---- 8 kt MMA steps over this chunk ---------------------------------
#pragma unroll
        for (int kt = 0; kt < 8; ++kt) {
            unsigned a0, a1, a2, a3;
            const unsigned ga = (unsigned)(kt * 2) + ahi;
            ldsm_x4(a0, a1, a2, a3, arow + ((ga ^ arx) << 4));

            unsigned b00, b01, b10, b11;
            const unsigned gb = (unsigned)(kt * 2) + bsel;
            ldsm_x4(b00, b01, b10, b11, brow + ((gb ^ bnx) << 4));

            mma16816(d0, a0, a1, a2, a3, b00, b01);
            mma16816(d1, a0, a1, a2, a3, b10, b11);
            mma16816(d2, a0, a1, a2, a3, bone, bone);
        }
        __syncwarp();   // chunk buffers free to overwrite
    }

    // -------- writeback: S[t][m] = exp(-sub[t][m]) ---------------------------
    float z0_lane0;
    {
        const float zlo = __shfl_sync(0xffffffffu, d2[0], lane & ~3);
        const float zhi = __shfl_sync(0xffffffffu, d2[2], lane & ~3);
        z0_lane0 = __shfl_sync(0xffffffffu, d2[0], 0);   // Z[0]
        const float rzlo = -__fdividef(1.0f, zlo);
        const float rzhi = -__fdividef(1.0f, zhi);

        const int tq = lane >> 2;
        const int mc = (lane & 3) * 2;
        *(float2*)(S + tq * SSTRIDE + mc) =
            make_float2(__expf(d0[0] * rzlo), __expf(d0[1] * rzlo));
        *(float2*)(S + (tq + 8) * SSTRIDE + mc) =
            make_float2(__expf(d0[2] * rzhi), __expf(d0[3] * rzhi));
        *(float2*)(S + tq * SSTRIDE + mc + 8) =
            make_float2(__expf(d1[0] * rzlo), __expf(d1[1] * rzlo));
        *(float2*)(S + (tq + 8) * SSTRIDE + mc + 8) =
            make_float2(__expf(d1[2] * rzhi), __expf(d1[3] * rzhi));
    }
    __syncwarp();

    // -------- soft-DP wavefront in w-domain (w = exp(-dp)) -------------------
    // w(i,j) = e^-10 * (w_up + w_left) + w_diag * exp(-sub[i-1][j-1])
    const float em1 = __expf(-10.0f * (float)(m + 1));   // w(0, m+1)
    const float em  = __expf(-10.0f * (float)m);         // w(0, m)
    float bl = K10;    // lane-0 running e^{-10*i}
    float bd = 1.0f;   // lane-0 running e^{-10*(i-1)}

    float cur = 0.0f, prev = 0.0f;
#pragma unroll
    for (int s = 0; s <= 30; ++s) {
        float leftv = __shfl_up_sync(0xffffffffu, cur, 1);
        float diagv = __shfl_up_sync(0xffffffffu, prev, 1);
        const int i = s - m + 1;
        const bool active = (i >= 1) && (i <= 16);

        float up = cur;
        if (i == 1) { up = em1; diagv = em; }
        if (m == 0) { leftv = bl; diagv = bd; }

        const int si = active ? (s - m) : 0;
        const float es = S[si * SSTRIDE + m];

        const float val = K10 * (up + leftv) + diagv * es;

        if (active) { prev = cur; cur = val; }
        bd = bl; bl *= K10;
    }

    // -------- final log + first-char term + output ---------------------------
    if (lane == 15) {
        const float fm = __expf(__ldg(lg + g0)) * __fdividef(1.0f, z0_lane0);
        out[b] = -__logf(cur) + FIRST_CHAR_COST * (1.0f - fm);
    }
}

extern "C" void kernel_launch(void* const* d_in, const int* in_sizes, int n_in,
                              void* d_out, int out_size)
{
    const float* logits = (const float*)d_in[0];   // tail_logits (B,T,V) f32
    const int*   tgt    = (const int*)  d_in[1];   // target_idx  (B,M) i32
    const float* phon   = (const float*)d_in[2];   // phon_cost   (V,V) f32
    float* out = (float*)d_out;
    const int B = out_size;                        // 8192

    const int grid = (B + WARPS_PER_BLOCK - 1) / WARPS_PER_BLOCK;
    rhyme_dp_kernel<<<grid, THREADS_PER_BLOCK>>>(logits, tgt, phon, out, B);
}

// round 12
// speedup vs baseline: 1.3433x; 1.2829x over previous
#include <cuda_runtime.h>
#include <cuda_fp16.h>

// B=8192, T=16, M=16, V=256 fixed.
#define INS_DEL 10.0f
#define FIRST_CHAR_COST 10.0f

#define WARPS_PER_BLOCK 4
#define THREADS_PER_BLOCK (WARPS_PER_BLOCK * 32)

#define K10 4.5399929762484854e-05f          // e^{-10}

// Per-warp shared: E[t][v] half (raw exp), row stride 264 halves (528B = 33
// granules -> ldmatrix conflict-free); S[t][m] = exp(-sub) fp32, stride 18.
#define PSTR 264
#define P_BYTES (16 * PSTR * 2)              // 8448
#define SSTRIDE 18
#define S_BYTES (16 * SSTRIDE * 4)           // 1152
#define WARP_SMEM_BYTES (P_BYTES + S_BYTES)  // 9600
#define SMEM_BYTES (WARPS_PER_BLOCK * WARP_SMEM_BYTES)

// phon_cost as fp16, columns permuted into mma-B-fragment order:
// dst pos kt*16 + tig*4 + {0,1,2,3}  <-  orig k = kt*16 + {2tig,2tig+1,2tig+8,2tig+9}
// so one aligned 8-byte load per (row, kt) yields both b-registers.
__device__ __half g_phon_frag[256 * 256];

__global__ void build_phon_frag(const float* __restrict__ phon) {
    const int tid = blockIdx.x * blockDim.x + threadIdx.x;   // 16384 threads
    const int r   = tid >> 6;          // row 0..255
    const int q   = tid & 63;          // group: kt*4 + tig
    const int kt  = q >> 2;
    const int tig = q & 3;
    const float* src = phon + r * 256 + kt * 16 + tig * 2;
    const float2 a = *(const float2*)(src);       // k = 2tig, 2tig+1
    const float2 c = *(const float2*)(src + 8);   // k = 2tig+8, 2tig+9
    __half2 h0 = __floats2half2_rn(a.x, a.y);
    __half2 h1 = __floats2half2_rn(c.x, c.y);
    ((uint2*)g_phon_frag)[tid] = make_uint2(*(unsigned*)&h0, *(unsigned*)&h1);
}

__device__ __forceinline__ void ldsm_x4(unsigned &r0, unsigned &r1,
                                        unsigned &r2, unsigned &r3,
                                        unsigned saddr) {
    asm volatile("ldmatrix.sync.aligned.m8n8.x4.shared.b16 {%0,%1,%2,%3}, [%4];\n"
                 : "=r"(r0), "=r"(r1), "=r"(r2), "=r"(r3) : "r"(saddr));
}

__device__ __forceinline__ void mma16816(float d[4],
                                         unsigned a0, unsigned a1,
                                         unsigned a2, unsigned a3,
                                         unsigned b0, unsigned b1) {
    asm volatile("mma.sync.aligned.m16n8k16.row.col.f32.f16.f16.f32 "
                 "{%0,%1,%2,%3}, {%4,%5,%6,%7}, {%8,%9}, {%0,%1,%2,%3};\n"
                 : "+f"(d[0]), "+f"(d[1]), "+f"(d[2]), "+f"(d[3])
                 : "r"(a0), "r"(a1), "r"(a2), "r"(a3), "r"(b0), "r"(b1));
}

__device__ __forceinline__ unsigned pack_h2(float x, float y) {
    __half2 h = __floats2half2_rn(x, y);
    return *(unsigned*)&h;
}

__global__ void __launch_bounds__(THREADS_PER_BLOCK, 5)
rhyme_dp_kernel(const float* __restrict__ logits,
                const int* __restrict__ tgt,
                float* __restrict__ out, int B)
{
    extern __shared__ char smem[];
    const int w    = threadIdx.x >> 5;
    const int lane = threadIdx.x & 31;
    const int b    = blockIdx.x * WARPS_PER_BLOCK + w;
    if (b >= B) return;

    __half* E = (__half*)(smem + w * WARP_SMEM_BYTES);
    float*  S = (float*)(smem + w * WARP_SMEM_BYTES + P_BYTES);

    const float* lg = logits + (size_t)b * (16 * 256);
    const int m = lane & 15;

    const int gm = tgt[b * 16 + m];
    const int g0 = __shfl_sync(0xffffffffu, gm, 0);

    // -------- Phase 1: raw exp -> shared E (half). No reductions. ----------
    {
        const float4* rows = (const float4*)lg;   // 16 rows x 64 float4
        const int li = lane * 2;
#pragma unroll
        for (int t = 0; t < 16; ++t) {
            float4 x0 = rows[t * 64 + li];
            float4 x1 = rows[t * 64 + li + 1];
            unsigned h[4];
            h[0] = pack_h2(__expf(x0.x), __expf(x0.y));
            h[1] = pack_h2(__expf(x0.z), __expf(x0.w));
            h[2] = pack_h2(__expf(x1.x), __expf(x1.y));
            h[3] = pack_h2(__expf(x1.z), __expf(x1.w));
            *(uint4*)(E + t * PSTR + lane * 8) = *(uint4*)h;
        }
    }
    __syncwarp();

    // -------- Phase 2: [sub_raw | Z] = E @ [C_gather | ones] via HMMA -------
    // B fragments: ONE aligned LDG.64 per (row, kt) from the fragment-
    // permuted fp16 table. Third n-tile = ones -> Z[t] in d2 col 0.
    float d0[4] = {0.f, 0.f, 0.f, 0.f};
    float d1[4] = {0.f, 0.f, 0.f, 0.f};
    float d2[4] = {0.f, 0.f, 0.f, 0.f};
    float z0_lane0;
    {
        unsigned pbase = (unsigned)__cvta_generic_to_shared(E);
        unsigned abase = pbase + (unsigned)((lane & 15) * (PSTR * 2) + (lane >> 4) * 16);

        const int gn0 = __shfl_sync(0xffffffffu, gm, lane >> 2);
        const int gn1 = __shfl_sync(0xffffffffu, gm, 8 + (lane >> 2));
        const int tig = lane & 3;
        const __half* fr0 = g_phon_frag + (size_t)gn0 * 256 + tig * 4;
        const __half* fr1 = g_phon_frag + (size_t)gn1 * 256 + tig * 4;

        const unsigned bone = (lane < 4) ? pack_h2(1.0f, 1.0f) : 0u;

#pragma unroll
        for (int kt = 0; kt < 16; ++kt) {
            unsigned a0, a1, a2, a3;
            ldsm_x4(a0, a1, a2, a3, abase + kt * 32);

            const uint2 u0 = __ldg((const uint2*)(fr0 + kt * 16));
            const uint2 u1 = __ldg((const uint2*)(fr1 + kt * 16));

            mma16816(d0, a0, a1, a2, a3, u0.x, u0.y);
            mma16816(d1, a0, a1, a2, a3, u1.x, u1.y);
            mma16816(d2, a0, a1, a2, a3, bone, bone);
        }

        // -------- writeback: S[t][m] = exp(-sub[t][m]) ----------------------
        const float zlo = __shfl_sync(0xffffffffu, d2[0], lane & ~3);
        const float zhi = __shfl_sync(0xffffffffu, d2[2], lane & ~3);
        z0_lane0 = __shfl_sync(0xffffffffu, d2[0], 0);   // Z[0]
        const float rzlo = -__fdividef(1.0f, zlo);
        const float rzhi = -__fdividef(1.0f, zhi);

        const int tq = lane >> 2;
        const int mc = tig * 2;
        *(float2*)(S + tq * SSTRIDE + mc) =
            make_float2(__expf(d0[0] * rzlo), __expf(d0[1] * rzlo));
        *(float2*)(S + (tq + 8) * SSTRIDE + mc) =
            make_float2(__expf(d0[2] * rzhi), __expf(d0[3] * rzhi));
        *(float2*)(S + tq * SSTRIDE + mc + 8) =
            make_float2(__expf(d1[0] * rzlo), __expf(d1[1] * rzlo));
        *(float2*)(S + (tq + 8) * SSTRIDE + mc + 8) =
            make_float2(__expf(d1[2] * rzhi), __expf(d1[3] * rzhi));
    }
    __syncwarp();

    // -------- Phase 3: soft-DP wavefront in w-domain (w = exp(-dp)) ---------
    // w(i,j) = e^-10 * (w_up + w_left) + w_diag * exp(-sub[i-1][j-1])
    const float em1 = __expf(-10.0f * (float)(m + 1));   // w(0, m+1)
    const float em  = __expf(-10.0f * (float)m);         // w(0, m)
    float bl = K10;    // lane-0 running e^{-10*i}
    float bd = 1.0f;   // lane-0 running e^{-10*(i-1)}

    float cur = 0.0f, prev = 0.0f;
#pragma unroll
    for (int s = 0; s <= 30; ++s) {
        float leftv = __shfl_up_sync(0xffffffffu, cur, 1);
        float diagv = __shfl_up_sync(0xffffffffu, prev, 1);
        const int i = s - m + 1;
        const bool active = (i >= 1) && (i <= 16);

        float up = cur;
        if (i == 1) { up = em1; diagv = em; }
        if (m == 0) { leftv = bl; diagv = bd; }

        const int si = active ? (s - m) : 0;
        const float es = S[si * SSTRIDE + m];

        const float val = K10 * (up + leftv) + diagv * es;

        if (active) { prev = cur; cur = val; }
        bd = bl; bl *= K10;
    }

    // -------- Phase 4: final log + first-char term + output -----------------
    if (lane == 15) {
        const float fm = __half2float(E[g0]) * __fdividef(1.0f, z0_lane0);
        out[b] = -__logf(cur) + FIRST_CHAR_COST * (1.0f - fm);
    }
}

extern "C" void kernel_launch(void* const* d_in, const int* in_sizes, int n_in,
                              void* d_out, int out_size)
{
    const float* logits = (const float*)d_in[0];   // tail_logits (B,T,V) f32
    const int*   tgt    = (const int*)  d_in[1];   // target_idx  (B,M) i32
    const float* phon   = (const float*)d_in[2];   // phon_cost   (V,V) f32
    float* out = (float*)d_out;
    const int B = out_size;                        // 8192

    // Prologue: fragment-permuted fp16 phon table (16384 threads, 1 uint2 ea).
    build_phon_frag<<<64, 256>>>(phon);

    cudaFuncSetAttribute(rhyme_dp_kernel,
                         cudaFuncAttributeMaxDynamicSharedMemorySize,
                         SMEM_BYTES);
    const int grid = (B + WARPS_PER_BLOCK - 1) / WARPS_PER_BLOCK;
    rhyme_dp_kernel<<<grid, THREADS_PER_BLOCK, SMEM_BYTES>>>(
        logits, tgt, out, B);
}